// round 16
// baseline (speedup 1.0000x reference)
#include <cuda_runtime.h>
#include <cuda_fp16.h>
#include <cstdint>
#include <cstddef>

// ---------------------------------------------------------------------------
// Problem constants
// ---------------------------------------------------------------------------
#define DIMC   1024
#define NHEADS 16
#define HDIM   64
#define NTOK   4096
#define BATCH  8
#define RR     206       // 103 blocks * 2 parities
#define SP     20        // tokens per patch
#define K3     3072      // 3*DIM

#define MROWS  (BATCH*NTOK)    // 32768 (both GEMMs, compact)

// ---------------------------------------------------------------------------
// Device scratch
// ---------------------------------------------------------------------------
__device__ __align__(16) __half  g_qkv_h[(size_t)MROWS * K3];     // fp16 qkv
__device__ __align__(16) __half  g_x_h[(size_t)MROWS * DIMC];     // A of GEMM1
__device__ __align__(16) __half  g_att_h[(size_t)MROWS * DIMC];   // A of GEMM2
__device__ __align__(16) __half  g_wq_h[(size_t)K3 * DIMC];       // B of GEMM1
__device__ __align__(16) __half  g_wo_h[(size_t)DIMC * DIMC];     // B of GEMM2

// ---------------------------------------------------------------------------
// Helpers
// ---------------------------------------------------------------------------
__device__ __forceinline__ uint32_t smem_to_u32(const void* p) {
    uint32_t a;
    asm("{ .reg .u64 t; cvta.to.shared.u64 t, %1; cvt.u32.u64 %0, t; }"
        : "=r"(a) : "l"(p));
    return a;
}

__device__ __forceinline__ uint32_t pack_h(__half a, __half b) {
    return (uint32_t)__half_as_ushort(a) | ((uint32_t)__half_as_ushort(b) << 16);
}

__device__ __forceinline__ uint2 h4(const float4 v) {
    uint2 r;
    r.x = pack_h(__float2half_rn(v.x), __float2half_rn(v.y));
    r.y = pack_h(__float2half_rn(v.z), __float2half_rn(v.w));
    return r;
}

__device__ __forceinline__ float4 u2f4(const uint2 p) {
    __half2 h0 = *(const __half2*)&p.x;
    __half2 h1 = *(const __half2*)&p.y;
    float2 f0 = __half22float2(h0);
    float2 f1 = __half22float2(h1);
    return make_float4(f0.x, f0.y, f1.x, f1.y);
}

#define LDSM4(r, addr) \
    asm volatile("ldmatrix.sync.aligned.m8n8.x4.shared.b16 {%0,%1,%2,%3}, [%4];" \
        : "=r"((r)[0]), "=r"((r)[1]), "=r"((r)[2]), "=r"((r)[3]) : "r"(addr))

#define MMA16816(d, a, b0, b1) \
    asm volatile("mma.sync.aligned.m16n8k16.row.col.f32.f16.f16.f32 " \
        "{%0,%1,%2,%3}, {%4,%5,%6,%7}, {%8,%9}, {%0,%1,%2,%3};" \
        : "+f"((d)[0]), "+f"((d)[1]), "+f"((d)[2]), "+f"((d)[3]) \
        : "r"((a)[0]), "r"((a)[1]), "r"((a)[2]), "r"((a)[3]), "r"(b0), "r"(b1))

#define CP_ASYNC16(dst, src) \
    asm volatile("cp.async.cg.shared.global [%0], [%1], 16;" :: "r"(dst), "l"(src))
#define CP_COMMIT() asm volatile("cp.async.commit_group;" ::: "memory")
#define CP_WAIT(n)  asm volatile("cp.async.wait_group %0;" :: "n"(n) : "memory")

// ---------------------------------------------------------------------------
// Merged conversion prepass: x, Wqkv, Wout -> fp16
// ---------------------------------------------------------------------------
#define NF4_X  ((size_t)MROWS * DIMC / 4)          // 8388608
#define NF4_WQ ((size_t)K3 * DIMC / 4)             // 786432
#define NF4_WO ((size_t)DIMC * DIMC / 4)           // 262144
#define CONV_BLOCKS ((NF4_X + NF4_WQ + NF4_WO) / 256)

__global__ void __launch_bounds__(256) conv_all(const float* __restrict__ x,
                                                const float* __restrict__ wq,
                                                const float* __restrict__ wo) {
    size_t i = (size_t)blockIdx.x * 256 + threadIdx.x;   // one float4
    if (i < NF4_X) {
        size_t e = i * 4;
        *(uint2*)(g_x_h + e) = h4(*(const float4*)(x + e));
    } else if (i < NF4_X + NF4_WQ) {
        size_t e = (i - NF4_X) * 4;
        *(uint2*)(g_wq_h + e) = h4(*(const float4*)(wq + e));
    } else {
        size_t e = (i - NF4_X - NF4_WQ) * 4;
        *(uint2*)(g_wo_h + e) = h4(*(const float4*)(wo + e));
    }
}

// ---------------------------------------------------------------------------
// fp16 mma.sync GEMM (R14 config — best measured): CTA 128x128, 4 warps
// (warp tile 64x64), BK=32, 6-stage cp.async pipeline, single barrier per
// k-iter, 2 CTAs/SM.
// MODE 0 stores fp16 (qkv scratch); MODE 1 stores fp32 + bias (final out).
// ---------------------------------------------------------------------------
#define BK      32
#define NSTAGE  6
#define STAGE   16384
#define OFF_A   0
#define OFF_B   8192
#define SMEM_TOTAL (NSTAGE*STAGE)   // 98304

template<int MODE>
__global__ void __launch_bounds__(128, 2)
gemm_mma(const float* __restrict__ bias, float* __restrict__ Cout, int Ncols)
{
    extern __shared__ char smem[];
    const uint32_t sbase = smem_to_u32(smem);
    const int tid  = threadIdx.x;
    const int lane = tid & 31;
    const int wid  = tid >> 5;   // 0..3
    const int wm   = wid >> 1;   // 0..1
    const int wn   = wid & 1;    // 0..1
    const int m0   = blockIdx.y * 128;
    const int n0   = blockIdx.x * 128;

    const char* bA = (const char*)((MODE == 0) ? g_x_h : g_att_h);
    const char* bB = (const char*)((MODE == 0) ? g_wq_h : g_wo_h);

    // cp.async: 4 chunks of 16B per thread per region; 32-bit byte offsets
    uint32_t dsto[4], aoff[4], boff[4];
    #pragma unroll
    for (int j = 0; j < 4; j++) {
        int c = tid + j * 128;
        int row = c >> 2, col = c & 3;
        dsto[j] = (uint32_t)(row * 64 + (((uint32_t)col ^ (((uint32_t)row >> 1) & 3)) << 4));
        aoff[j] = (uint32_t)((m0 + row) * DIMC + col * 8) * 2u;
        boff[j] = (uint32_t)((n0 + row) * DIMC + col * 8) * 2u;
    }

    uint32_t aOff[4], aXor[4];
    #pragma unroll
    for (int mf = 0; mf < 4; mf++) {
        int row = wm * 64 + mf * 16 + (lane & 15);
        aOff[mf] = (uint32_t)row * 64;
        aXor[mf] = ((uint32_t)row >> 1) & 3;
    }
    const uint32_t aHi = (uint32_t)(lane >> 4);
    uint32_t bOff[4], bXor[4];
    #pragma unroll
    for (int g = 0; g < 4; g++) {
        int row = wn * 64 + (lane & 7) + ((lane >> 4) << 3) + g * 16;
        bOff[g] = (uint32_t)row * 64;
        bXor[g] = ((uint32_t)row >> 1) & 3;
    }
    const uint32_t bk = (uint32_t)((lane >> 3) & 1);

    float acc[4][8][4];
    #pragma unroll
    for (int i = 0; i < 4; i++)
        #pragma unroll
        for (int j = 0; j < 8; j++)
            #pragma unroll
            for (int q = 0; q < 4; q++) acc[i][j][q] = 0.f;

    const int NIT = DIMC / BK;   // 32

    #define ISSUE_TILE(tile) do {                                             \
        const uint32_t sd = sbase + (uint32_t)((tile) % NSTAGE) * STAGE;      \
        const uint32_t kb = (uint32_t)(tile) * (BK * 2);                      \
        _Pragma("unroll")                                                     \
        for (int j = 0; j < 4; j++) {                                         \
            CP_ASYNC16(sd + OFF_A + dsto[j], bA + aoff[j] + kb);              \
            CP_ASYNC16(sd + OFF_B + dsto[j], bB + boff[j] + kb);              \
        }                                                                     \
        CP_COMMIT();                                                          \
    } while (0)

    ISSUE_TILE(0); ISSUE_TILE(1); ISSUE_TILE(2); ISSUE_TILE(3); ISSUE_TILE(4);

    #pragma unroll 1
    for (int it = 0; it < NIT; ++it) {
        if      (it <  NIT - 4) { CP_WAIT(4); }
        else if (it == NIT - 4) { CP_WAIT(3); }
        else if (it == NIT - 3) { CP_WAIT(2); }
        else if (it == NIT - 2) { CP_WAIT(1); }
        else                    { CP_WAIT(0); }
        __syncthreads();
        if (it + 5 < NIT) ISSUE_TILE(it + 5);

        const uint32_t s = sbase + (uint32_t)(it % NSTAGE) * STAGE;
        #pragma unroll
        for (int ks = 0; ks < 2; ++ks) {
            uint32_t ahi[4][4];
            #pragma unroll
            for (int mf = 0; mf < 4; mf++) {
                uint32_t c = (((uint32_t)(ks * 2) + aHi) ^ aXor[mf]) << 4;
                LDSM4(ahi[mf], s + OFF_A + aOff[mf] + c);
            }
            #pragma unroll
            for (int g = 0; g < 4; g++) {
                uint32_t bh[4];
                uint32_t c = (((uint32_t)(ks * 2) + bk) ^ bXor[g]) << 4;
                LDSM4(bh, s + OFF_B + bOff[g] + c);
                #pragma unroll
                for (int mf = 0; mf < 4; mf++) {
                    MMA16816(acc[mf][2 * g],     ahi[mf], bh[0], bh[1]);
                    MMA16816(acc[mf][2 * g + 1], ahi[mf], bh[2], bh[3]);
                }
            }
        }
    }
    #undef ISSUE_TILE

    // Epilogue
    const int grp = lane >> 2;
    const int thr = lane & 3;
    #pragma unroll
    for (int mf = 0; mf < 4; mf++) {
        const int mrow = m0 + wm * 64 + mf * 16 + grp;
        #pragma unroll
        for (int nf = 0; nf < 8; nf++) {
            const int col = n0 + wn * 64 + nf * 8 + thr * 2;
            if (MODE == 0) {
                __half* Ch = g_qkv_h;
                *(uint32_t*)(Ch + (size_t)mrow * Ncols + col) =
                    pack_h(__float2half_rn(acc[mf][nf][0]), __float2half_rn(acc[mf][nf][1]));
                *(uint32_t*)(Ch + (size_t)(mrow + 8) * Ncols + col) =
                    pack_h(__float2half_rn(acc[mf][nf][2]), __float2half_rn(acc[mf][nf][3]));
            } else {
                const float2 bv = *(const float2*)(bias + col);
                float2 v0 = make_float2(acc[mf][nf][0] + bv.x, acc[mf][nf][1] + bv.y);
                float2 v1 = make_float2(acc[mf][nf][2] + bv.x, acc[mf][nf][3] + bv.y);
                *(float2*)(Cout + (size_t)mrow * Ncols + col)       = v0;
                *(float2*)(Cout + (size_t)(mrow + 8) * Ncols + col) = v1;
            }
        }
    }
}

// ---------------------------------------------------------------------------
// Per-patch attention — 128 threads/block (better resident-block count and
// busy-thread fraction; per-phase work assignments and math UNCHANGED).
// fp16 q/k/v in smem; fp32 math.
// ---------------------------------------------------------------------------
#define HSTR 72   // halves per row (144 B, multiple of 16)
__global__ void __launch_bounds__(128) attn_kernel()
{
    const int r   = blockIdx.x;
    const int h   = blockIdx.y;
    const int b   = blockIdx.z;
    const int blk = r >> 1, par = r & 1;

    __shared__ __half qh[SP * HSTR];
    __shared__ __half kh[SP * HSTR];
    __shared__ __half vh[SP * HSTR];
    __shared__ float dots[SP][SP + 1];

    const int tid = threadIdx.x;
    const size_t base = (size_t)b * NTOK * K3;

    for (int i = tid; i < SP * 16; i += 128) {
        int s = i >> 4, j = i & 15;
        int n = blk * 40 + par + 2 * s;
        uint2 qv, kv, vv;
        if (n < NTOK) {
            const __half* rp = g_qkv_h + base + (size_t)n * K3 + h * HDIM;
            qv = ((const uint2*)(rp))[j];
            kv = ((const uint2*)(rp + DIMC))[j];
            vv = ((const uint2*)(rp + 2 * DIMC))[j];
        } else {
            qv = kv = vv = make_uint2(0u, 0u);
        }
        *(uint2*)(qh + s * HSTR + 4 * j) = qv;
        *(uint2*)(kh + s * HSTR + 4 * j) = kv;
        *(uint2*)(vh + s * HSTR + 4 * j) = vv;
    }
    __syncthreads();

    const float scale = 0.125f;  // 64^-0.5
    if (tid < 100) {
        const int a  = tid / 10;
        const int bq = tid % 10;
        const uint4* q0 = (const uint4*)(qh + a * HSTR);
        const uint4* q1 = (const uint4*)(qh + (a + 10) * HSTR);
        const uint4* k0 = (const uint4*)(kh + bq * HSTR);
        const uint4* k1 = (const uint4*)(kh + (bq + 10) * HSTR);
        float d00 = 0.f, d01 = 0.f, d10 = 0.f, d11 = 0.f;
        #pragma unroll
        for (int e8 = 0; e8 < 8; e8++) {
            uint4 qa = q0[e8], qb = q1[e8];
            uint4 ka = k0[e8], kb2 = k1[e8];
            float4 a0 = u2f4(make_uint2(qa.x, qa.y)), a0b = u2f4(make_uint2(qa.z, qa.w));
            float4 a1 = u2f4(make_uint2(qb.x, qb.y)), a1b = u2f4(make_uint2(qb.z, qb.w));
            float4 c0 = u2f4(make_uint2(ka.x, ka.y)), c0b = u2f4(make_uint2(ka.z, ka.w));
            float4 c1 = u2f4(make_uint2(kb2.x, kb2.y)), c1b = u2f4(make_uint2(kb2.z, kb2.w));
            d00 = fmaf(a0.x, c0.x, d00); d00 = fmaf(a0.y, c0.y, d00);
            d00 = fmaf(a0.z, c0.z, d00); d00 = fmaf(a0.w, c0.w, d00);
            d00 = fmaf(a0b.x, c0b.x, d00); d00 = fmaf(a0b.y, c0b.y, d00);
            d00 = fmaf(a0b.z, c0b.z, d00); d00 = fmaf(a0b.w, c0b.w, d00);
            d01 = fmaf(a0.x, c1.x, d01); d01 = fmaf(a0.y, c1.y, d01);
            d01 = fmaf(a0.z, c1.z, d01); d01 = fmaf(a0.w, c1.w, d01);
            d01 = fmaf(a0b.x, c1b.x, d01); d01 = fmaf(a0b.y, c1b.y, d01);
            d01 = fmaf(a0b.z, c1b.z, d01); d01 = fmaf(a0b.w, c1b.w, d01);
            d10 = fmaf(a1.x, c0.x, d10); d10 = fmaf(a1.y, c0.y, d10);
            d10 = fmaf(a1.z, c0.z, d10); d10 = fmaf(a1.w, c0.w, d10);
            d10 = fmaf(a1b.x, c0b.x, d10); d10 = fmaf(a1b.y, c0b.y, d10);
            d10 = fmaf(a1b.z, c0b.z, d10); d10 = fmaf(a1b.w, c0b.w, d10);
            d11 = fmaf(a1.x, c1.x, d11); d11 = fmaf(a1.y, c1.y, d11);
            d11 = fmaf(a1.z, c1.z, d11); d11 = fmaf(a1.w, c1.w, d11);
            d11 = fmaf(a1b.x, c1b.x, d11); d11 = fmaf(a1b.y, c1b.y, d11);
            d11 = fmaf(a1b.z, c1b.z, d11); d11 = fmaf(a1b.w, c1b.w, d11);
        }
        dots[a][bq]            = d00 * scale;
        dots[a][bq + 10]       = d01 * scale;
        dots[a + 10][bq]       = d10 * scale;
        dots[a + 10][bq + 10]  = d11 * scale;
    }
    __syncthreads();

    if (tid < SP) {
        float mx = -1e30f;
        #pragma unroll
        for (int t = 0; t < SP; t++) mx = fmaxf(mx, dots[tid][t]);
        float ex[SP]; float sum = 0.f;
        #pragma unroll
        for (int t = 0; t < SP; t++) { float e = expf(dots[tid][t] - mx); ex[t] = e; sum += e; }
        float inv = 1.f / sum;
        #pragma unroll
        for (int t = 0; t < SP; t++) dots[tid][t] = ex[t] * inv;
    }
    __syncthreads();

    if (tid < 80) {
        const int sg = tid >> 4;     // 0..4
        const int e4 = tid & 15;
        const int s0 = sg, s1 = sg + 5, s2 = sg + 10, s3 = sg + 15;
        float4 a0 = make_float4(0.f, 0.f, 0.f, 0.f);
        float4 a1 = a0, a2 = a0, a3 = a0;
        #pragma unroll
        for (int t = 0; t < SP; t++) {
            float w0 = dots[s0][t], w1 = dots[s1][t];
            float w2 = dots[s2][t], w3 = dots[s3][t];
            float4 vv = u2f4(*(const uint2*)(vh + t * HSTR + 4 * e4));
            a0.x = fmaf(w0, vv.x, a0.x); a0.y = fmaf(w0, vv.y, a0.y);
            a0.z = fmaf(w0, vv.z, a0.z); a0.w = fmaf(w0, vv.w, a0.w);
            a1.x = fmaf(w1, vv.x, a1.x); a1.y = fmaf(w1, vv.y, a1.y);
            a1.z = fmaf(w1, vv.z, a1.z); a1.w = fmaf(w1, vv.w, a1.w);
            a2.x = fmaf(w2, vv.x, a2.x); a2.y = fmaf(w2, vv.y, a2.y);
            a2.z = fmaf(w2, vv.z, a2.z); a2.w = fmaf(w2, vv.w, a2.w);
            a3.x = fmaf(w3, vv.x, a3.x); a3.y = fmaf(w3, vv.y, a3.y);
            a3.z = fmaf(w3, vv.z, a3.z); a3.w = fmaf(w3, vv.w, a3.w);
        }
        const int ss[4] = { s0, s1, s2, s3 };
        float4 res[4] = { a0, a1, a2, a3 };
        #pragma unroll
        for (int j = 0; j < 4; j++) {
            int n = blk * 40 + par + 2 * ss[j];
            if (n < NTOK) {
                size_t idx = ((size_t)b * NTOK + n) * DIMC + h * HDIM + e4 * 4;
                *(uint2*)(g_att_h + idx) = h4(res[j]);
            }
        }
    }
}

// ---------------------------------------------------------------------------
extern "C" void kernel_launch(void* const* d_in, const int* in_sizes, int n_in,
                              void* d_out, int out_size)
{
    const float* x    = (const float*)d_in[0];  // (8, 4096, 1024)
    const float* Wqkv = (const float*)d_in[1];  // (3072, 1024)
    const float* Wout = (const float*)d_in[2];  // (1024, 1024)
    const float* bout = (const float*)d_in[3];  // (1024,)
    float* out = (float*)d_out;                 // (8, 4096, 1024)

    static bool attr_done = false;
    if (!attr_done) {
        cudaFuncSetAttribute(gemm_mma<0>, cudaFuncAttributeMaxDynamicSharedMemorySize, SMEM_TOTAL);
        cudaFuncSetAttribute(gemm_mma<1>, cudaFuncAttributeMaxDynamicSharedMemorySize, SMEM_TOTAL);
        attr_done = true;
    }

    // 0) Convert x, Wqkv, Wout -> fp16
    conv_all<<<(unsigned)CONV_BLOCKS, 256>>>(x, Wqkv, Wout);

    // 1) QKV projection: M=32768, N=3072, fp16 output
    gemm_mma<0><<<dim3(K3 / 128, MROWS / 128), 128, SMEM_TOTAL>>>(nullptr, nullptr, K3);

    // 2) Patch attention (fp16 in/out, fp32 math), 128 threads/block
    attn_kernel<<<dim3(RR, NHEADS, BATCH), 128>>>();

    // 3) Output projection + bias: M=32768, N=1024, fp32 output
    gemm_mma<1><<<dim3(DIMC / 128, MROWS / 128), 128, SMEM_TOTAL>>>(bout, out, DIMC);
}

// round 17
// speedup vs baseline: 1.4743x; 1.4743x over previous
#include <cuda_runtime.h>
#include <cuda_fp16.h>
#include <cstdint>
#include <cstddef>

// ---------------------------------------------------------------------------
// Problem constants
// ---------------------------------------------------------------------------
#define DIMC   1024
#define NHEADS 16
#define HDIM   64
#define NTOK   4096
#define BATCH  8
#define RR     206       // 103 blocks * 2 parities
#define SP     20        // tokens per patch
#define K3     3072      // 3*DIM

#define MROWS  (BATCH*NTOK)    // 32768 (both GEMMs, compact)

// ---------------------------------------------------------------------------
// Device scratch
// ---------------------------------------------------------------------------
__device__ __align__(16) __half  g_qkv_h[(size_t)MROWS * K3];     // fp16 qkv
__device__ __align__(16) __half  g_x_h[(size_t)MROWS * DIMC];     // A of GEMM1
__device__ __align__(16) __half  g_att_h[(size_t)MROWS * DIMC];   // A of GEMM2
__device__ __align__(16) __half  g_wq_h[(size_t)K3 * DIMC];       // B of GEMM1
__device__ __align__(16) __half  g_wo_h[(size_t)DIMC * DIMC];     // B of GEMM2

// ---------------------------------------------------------------------------
// Helpers
// ---------------------------------------------------------------------------
__device__ __forceinline__ uint32_t smem_to_u32(const void* p) {
    uint32_t a;
    asm("{ .reg .u64 t; cvta.to.shared.u64 t, %1; cvt.u32.u64 %0, t; }"
        : "=r"(a) : "l"(p));
    return a;
}

__device__ __forceinline__ uint32_t pack_h(__half a, __half b) {
    return (uint32_t)__half_as_ushort(a) | ((uint32_t)__half_as_ushort(b) << 16);
}

__device__ __forceinline__ uint2 h4(const float4 v) {
    uint2 r;
    r.x = pack_h(__float2half_rn(v.x), __float2half_rn(v.y));
    r.y = pack_h(__float2half_rn(v.z), __float2half_rn(v.w));
    return r;
}

__device__ __forceinline__ float4 u2f4(const uint2 p) {
    __half2 h0 = *(const __half2*)&p.x;
    __half2 h1 = *(const __half2*)&p.y;
    float2 f0 = __half22float2(h0);
    float2 f1 = __half22float2(h1);
    return make_float4(f0.x, f0.y, f1.x, f1.y);
}

#define LDSM4(r, addr) \
    asm volatile("ldmatrix.sync.aligned.m8n8.x4.shared.b16 {%0,%1,%2,%3}, [%4];" \
        : "=r"((r)[0]), "=r"((r)[1]), "=r"((r)[2]), "=r"((r)[3]) : "r"(addr))

#define MMA16816(d, a, b0, b1) \
    asm volatile("mma.sync.aligned.m16n8k16.row.col.f32.f16.f16.f32 " \
        "{%0,%1,%2,%3}, {%4,%5,%6,%7}, {%8,%9}, {%0,%1,%2,%3};" \
        : "+f"((d)[0]), "+f"((d)[1]), "+f"((d)[2]), "+f"((d)[3]) \
        : "r"((a)[0]), "r"((a)[1]), "r"((a)[2]), "r"((a)[3]), "r"(b0), "r"(b1))

#define CP_ASYNC16(dst, src) \
    asm volatile("cp.async.cg.shared.global [%0], [%1], 16;" :: "r"(dst), "l"(src))
#define CP_COMMIT() asm volatile("cp.async.commit_group;" ::: "memory")
#define CP_WAIT(n)  asm volatile("cp.async.wait_group %0;" :: "n"(n) : "memory")

// ---------------------------------------------------------------------------
// Merged conversion prepass: x, Wqkv, Wout -> fp16
// ---------------------------------------------------------------------------
#define NF4_X  ((size_t)MROWS * DIMC / 4)          // 8388608
#define NF4_WQ ((size_t)K3 * DIMC / 4)             // 786432
#define NF4_WO ((size_t)DIMC * DIMC / 4)           // 262144
#define CONV_BLOCKS ((NF4_X + NF4_WQ + NF4_WO) / 256)

__global__ void __launch_bounds__(256) conv_all(const float* __restrict__ x,
                                                const float* __restrict__ wq,
                                                const float* __restrict__ wo) {
    size_t i = (size_t)blockIdx.x * 256 + threadIdx.x;   // one float4
    if (i < NF4_X) {
        size_t e = i * 4;
        *(uint2*)(g_x_h + e) = h4(*(const float4*)(x + e));
    } else if (i < NF4_X + NF4_WQ) {
        size_t e = (i - NF4_X) * 4;
        *(uint2*)(g_wq_h + e) = h4(*(const float4*)(wq + e));
    } else {
        size_t e = (i - NF4_X - NF4_WQ) * 4;
        *(uint2*)(g_wo_h + e) = h4(*(const float4*)(wo + e));
    }
}

// ---------------------------------------------------------------------------
// fp16 mma.sync GEMM (R14 config — best measured): CTA 128x128, 4 warps
// (warp tile 64x64), BK=32, 6-stage cp.async pipeline, single barrier per
// k-iter, 2 CTAs/SM.
// MODE 0 stores fp16 (qkv scratch); MODE 1 stores fp32 + bias (final out).
// ---------------------------------------------------------------------------
#define BK      32
#define NSTAGE  6
#define STAGE   16384
#define OFF_A   0
#define OFF_B   8192
#define SMEM_TOTAL (NSTAGE*STAGE)   // 98304

template<int MODE>
__global__ void __launch_bounds__(128, 2)
gemm_mma(const float* __restrict__ bias, float* __restrict__ Cout, int Ncols)
{
    extern __shared__ char smem[];
    const uint32_t sbase = smem_to_u32(smem);
    const int tid  = threadIdx.x;
    const int lane = tid & 31;
    const int wid  = tid >> 5;   // 0..3
    const int wm   = wid >> 1;   // 0..1
    const int wn   = wid & 1;    // 0..1
    const int m0   = blockIdx.y * 128;
    const int n0   = blockIdx.x * 128;

    const char* bA = (const char*)((MODE == 0) ? g_x_h : g_att_h);
    const char* bB = (const char*)((MODE == 0) ? g_wq_h : g_wo_h);

    // cp.async: 4 chunks of 16B per thread per region; 32-bit byte offsets
    uint32_t dsto[4], aoff[4], boff[4];
    #pragma unroll
    for (int j = 0; j < 4; j++) {
        int c = tid + j * 128;
        int row = c >> 2, col = c & 3;
        dsto[j] = (uint32_t)(row * 64 + (((uint32_t)col ^ (((uint32_t)row >> 1) & 3)) << 4));
        aoff[j] = (uint32_t)((m0 + row) * DIMC + col * 8) * 2u;
        boff[j] = (uint32_t)((n0 + row) * DIMC + col * 8) * 2u;
    }

    uint32_t aOff[4], aXor[4];
    #pragma unroll
    for (int mf = 0; mf < 4; mf++) {
        int row = wm * 64 + mf * 16 + (lane & 15);
        aOff[mf] = (uint32_t)row * 64;
        aXor[mf] = ((uint32_t)row >> 1) & 3;
    }
    const uint32_t aHi = (uint32_t)(lane >> 4);
    uint32_t bOff[4], bXor[4];
    #pragma unroll
    for (int g = 0; g < 4; g++) {
        int row = wn * 64 + (lane & 7) + ((lane >> 4) << 3) + g * 16;
        bOff[g] = (uint32_t)row * 64;
        bXor[g] = ((uint32_t)row >> 1) & 3;
    }
    const uint32_t bk = (uint32_t)((lane >> 3) & 1);

    float acc[4][8][4];
    #pragma unroll
    for (int i = 0; i < 4; i++)
        #pragma unroll
        for (int j = 0; j < 8; j++)
            #pragma unroll
            for (int q = 0; q < 4; q++) acc[i][j][q] = 0.f;

    const int NIT = DIMC / BK;   // 32

    #define ISSUE_TILE(tile) do {                                             \
        const uint32_t sd = sbase + (uint32_t)((tile) % NSTAGE) * STAGE;      \
        const uint32_t kb = (uint32_t)(tile) * (BK * 2);                      \
        _Pragma("unroll")                                                     \
        for (int j = 0; j < 4; j++) {                                         \
            CP_ASYNC16(sd + OFF_A + dsto[j], bA + aoff[j] + kb);              \
            CP_ASYNC16(sd + OFF_B + dsto[j], bB + boff[j] + kb);              \
        }                                                                     \
        CP_COMMIT();                                                          \
    } while (0)

    ISSUE_TILE(0); ISSUE_TILE(1); ISSUE_TILE(2); ISSUE_TILE(3); ISSUE_TILE(4);

    #pragma unroll 1
    for (int it = 0; it < NIT; ++it) {
        if      (it <  NIT - 4) { CP_WAIT(4); }
        else if (it == NIT - 4) { CP_WAIT(3); }
        else if (it == NIT - 3) { CP_WAIT(2); }
        else if (it == NIT - 2) { CP_WAIT(1); }
        else                    { CP_WAIT(0); }
        __syncthreads();
        if (it + 5 < NIT) ISSUE_TILE(it + 5);

        const uint32_t s = sbase + (uint32_t)(it % NSTAGE) * STAGE;
        #pragma unroll
        for (int ks = 0; ks < 2; ++ks) {
            uint32_t ahi[4][4];
            #pragma unroll
            for (int mf = 0; mf < 4; mf++) {
                uint32_t c = (((uint32_t)(ks * 2) + aHi) ^ aXor[mf]) << 4;
                LDSM4(ahi[mf], s + OFF_A + aOff[mf] + c);
            }
            #pragma unroll
            for (int g = 0; g < 4; g++) {
                uint32_t bh[4];
                uint32_t c = (((uint32_t)(ks * 2) + bk) ^ bXor[g]) << 4;
                LDSM4(bh, s + OFF_B + bOff[g] + c);
                #pragma unroll
                for (int mf = 0; mf < 4; mf++) {
                    MMA16816(acc[mf][2 * g],     ahi[mf], bh[0], bh[1]);
                    MMA16816(acc[mf][2 * g + 1], ahi[mf], bh[2], bh[3]);
                }
            }
        }
    }
    #undef ISSUE_TILE

    // Epilogue
    const int grp = lane >> 2;
    const int thr = lane & 3;
    #pragma unroll
    for (int mf = 0; mf < 4; mf++) {
        const int mrow = m0 + wm * 64 + mf * 16 + grp;
        #pragma unroll
        for (int nf = 0; nf < 8; nf++) {
            const int col = n0 + wn * 64 + nf * 8 + thr * 2;
            if (MODE == 0) {
                __half* Ch = g_qkv_h;
                *(uint32_t*)(Ch + (size_t)mrow * Ncols + col) =
                    pack_h(__float2half_rn(acc[mf][nf][0]), __float2half_rn(acc[mf][nf][1]));
                *(uint32_t*)(Ch + (size_t)(mrow + 8) * Ncols + col) =
                    pack_h(__float2half_rn(acc[mf][nf][2]), __float2half_rn(acc[mf][nf][3]));
            } else {
                const float2 bv = *(const float2*)(bias + col);
                float2 v0 = make_float2(acc[mf][nf][0] + bv.x, acc[mf][nf][1] + bv.y);
                float2 v1 = make_float2(acc[mf][nf][2] + bv.x, acc[mf][nf][3] + bv.y);
                *(float2*)(Cout + (size_t)mrow * Ncols + col)       = v0;
                *(float2*)(Cout + (size_t)(mrow + 8) * Ncols + col) = v1;
            }
        }
    }
}

// ---------------------------------------------------------------------------
// Per-patch attention (R14 config — 256 threads). fp16 q/k/v in smem;
// fp32 math.
// ---------------------------------------------------------------------------
#define HSTR 72   // halves per row (144 B, multiple of 16)
__global__ void __launch_bounds__(256) attn_kernel()
{
    const int r   = blockIdx.x;
    const int h   = blockIdx.y;
    const int b   = blockIdx.z;
    const int blk = r >> 1, par = r & 1;

    __shared__ __half qh[SP * HSTR];
    __shared__ __half kh[SP * HSTR];
    __shared__ __half vh[SP * HSTR];
    __shared__ float dots[SP][SP + 1];

    const int tid = threadIdx.x;
    const size_t base = (size_t)b * NTOK * K3;

    for (int i = tid; i < SP * 16; i += 256) {
        int s = i >> 4, j = i & 15;
        int n = blk * 40 + par + 2 * s;
        uint2 qv, kv, vv;
        if (n < NTOK) {
            const __half* rp = g_qkv_h + base + (size_t)n * K3 + h * HDIM;
            qv = ((const uint2*)(rp))[j];
            kv = ((const uint2*)(rp + DIMC))[j];
            vv = ((const uint2*)(rp + 2 * DIMC))[j];
        } else {
            qv = kv = vv = make_uint2(0u, 0u);
        }
        *(uint2*)(qh + s * HSTR + 4 * j) = qv;
        *(uint2*)(kh + s * HSTR + 4 * j) = kv;
        *(uint2*)(vh + s * HSTR + 4 * j) = vv;
    }
    __syncthreads();

    const float scale = 0.125f;  // 64^-0.5
    if (tid < 100) {
        const int a  = tid / 10;
        const int bq = tid % 10;
        const uint4* q0 = (const uint4*)(qh + a * HSTR);
        const uint4* q1 = (const uint4*)(qh + (a + 10) * HSTR);
        const uint4* k0 = (const uint4*)(kh + bq * HSTR);
        const uint4* k1 = (const uint4*)(kh + (bq + 10) * HSTR);
        float d00 = 0.f, d01 = 0.f, d10 = 0.f, d11 = 0.f;
        #pragma unroll
        for (int e8 = 0; e8 < 8; e8++) {
            uint4 qa = q0[e8], qb = q1[e8];
            uint4 ka = k0[e8], kb2 = k1[e8];
            float4 a0 = u2f4(make_uint2(qa.x, qa.y)), a0b = u2f4(make_uint2(qa.z, qa.w));
            float4 a1 = u2f4(make_uint2(qb.x, qb.y)), a1b = u2f4(make_uint2(qb.z, qb.w));
            float4 c0 = u2f4(make_uint2(ka.x, ka.y)), c0b = u2f4(make_uint2(ka.z, ka.w));
            float4 c1 = u2f4(make_uint2(kb2.x, kb2.y)), c1b = u2f4(make_uint2(kb2.z, kb2.w));
            d00 = fmaf(a0.x, c0.x, d00); d00 = fmaf(a0.y, c0.y, d00);
            d00 = fmaf(a0.z, c0.z, d00); d00 = fmaf(a0.w, c0.w, d00);
            d00 = fmaf(a0b.x, c0b.x, d00); d00 = fmaf(a0b.y, c0b.y, d00);
            d00 = fmaf(a0b.z, c0b.z, d00); d00 = fmaf(a0b.w, c0b.w, d00);
            d01 = fmaf(a0.x, c1.x, d01); d01 = fmaf(a0.y, c1.y, d01);
            d01 = fmaf(a0.z, c1.z, d01); d01 = fmaf(a0.w, c1.w, d01);
            d01 = fmaf(a0b.x, c1b.x, d01); d01 = fmaf(a0b.y, c1b.y, d01);
            d01 = fmaf(a0b.z, c1b.z, d01); d01 = fmaf(a0b.w, c1b.w, d01);
            d10 = fmaf(a1.x, c0.x, d10); d10 = fmaf(a1.y, c0.y, d10);
            d10 = fmaf(a1.z, c0.z, d10); d10 = fmaf(a1.w, c0.w, d10);
            d10 = fmaf(a1b.x, c0b.x, d10); d10 = fmaf(a1b.y, c0b.y, d10);
            d10 = fmaf(a1b.z, c0b.z, d10); d10 = fmaf(a1b.w, c0b.w, d10);
            d11 = fmaf(a1.x, c1.x, d11); d11 = fmaf(a1.y, c1.y, d11);
            d11 = fmaf(a1.z, c1.z, d11); d11 = fmaf(a1.w, c1.w, d11);
            d11 = fmaf(a1b.x, c1b.x, d11); d11 = fmaf(a1b.y, c1b.y, d11);
            d11 = fmaf(a1b.z, c1b.z, d11); d11 = fmaf(a1b.w, c1b.w, d11);
        }
        dots[a][bq]            = d00 * scale;
        dots[a][bq + 10]       = d01 * scale;
        dots[a + 10][bq]       = d10 * scale;
        dots[a + 10][bq + 10]  = d11 * scale;
    }
    __syncthreads();

    if (tid < SP) {
        float mx = -1e30f;
        #pragma unroll
        for (int t = 0; t < SP; t++) mx = fmaxf(mx, dots[tid][t]);
        float ex[SP]; float sum = 0.f;
        #pragma unroll
        for (int t = 0; t < SP; t++) { float e = expf(dots[tid][t] - mx); ex[t] = e; sum += e; }
        float inv = 1.f / sum;
        #pragma unroll
        for (int t = 0; t < SP; t++) dots[tid][t] = ex[t] * inv;
    }
    __syncthreads();

    if (tid < 80) {
        const int sg = tid >> 4;     // 0..4
        const int e4 = tid & 15;
        const int s0 = sg, s1 = sg + 5, s2 = sg + 10, s3 = sg + 15;
        float4 a0 = make_float4(0.f, 0.f, 0.f, 0.f);
        float4 a1 = a0, a2 = a0, a3 = a0;
        #pragma unroll
        for (int t = 0; t < SP; t++) {
            float w0 = dots[s0][t], w1 = dots[s1][t];
            float w2 = dots[s2][t], w3 = dots[s3][t];
            float4 vv = u2f4(*(const uint2*)(vh + t * HSTR + 4 * e4));
            a0.x = fmaf(w0, vv.x, a0.x); a0.y = fmaf(w0, vv.y, a0.y);
            a0.z = fmaf(w0, vv.z, a0.z); a0.w = fmaf(w0, vv.w, a0.w);
            a1.x = fmaf(w1, vv.x, a1.x); a1.y = fmaf(w1, vv.y, a1.y);
            a1.z = fmaf(w1, vv.z, a1.z); a1.w = fmaf(w1, vv.w, a1.w);
            a2.x = fmaf(w2, vv.x, a2.x); a2.y = fmaf(w2, vv.y, a2.y);
            a2.z = fmaf(w2, vv.z, a2.z); a2.w = fmaf(w2, vv.w, a2.w);
            a3.x = fmaf(w3, vv.x, a3.x); a3.y = fmaf(w3, vv.y, a3.y);
            a3.z = fmaf(w3, vv.z, a3.z); a3.w = fmaf(w3, vv.w, a3.w);
        }
        const int ss[4] = { s0, s1, s2, s3 };
        float4 res[4] = { a0, a1, a2, a3 };
        #pragma unroll
        for (int j = 0; j < 4; j++) {
            int n = blk * 40 + par + 2 * ss[j];
            if (n < NTOK) {
                size_t idx = ((size_t)b * NTOK + n) * DIMC + h * HDIM + e4 * 4;
                *(uint2*)(g_att_h + idx) = h4(res[j]);
            }
        }
    }
}

// ---------------------------------------------------------------------------
extern "C" void kernel_launch(void* const* d_in, const int* in_sizes, int n_in,
                              void* d_out, int out_size)
{
    const float* x    = (const float*)d_in[0];  // (8, 4096, 1024)
    const float* Wqkv = (const float*)d_in[1];  // (3072, 1024)
    const float* Wout = (const float*)d_in[2];  // (1024, 1024)
    const float* bout = (const float*)d_in[3];  // (1024,)
    float* out = (float*)d_out;                 // (8, 4096, 1024)

    static bool attr_done = false;
    if (!attr_done) {
        cudaFuncSetAttribute(gemm_mma<0>, cudaFuncAttributeMaxDynamicSharedMemorySize, SMEM_TOTAL);
        cudaFuncSetAttribute(gemm_mma<1>, cudaFuncAttributeMaxDynamicSharedMemorySize, SMEM_TOTAL);
        attr_done = true;
    }

    // 0) Convert x, Wqkv, Wout -> fp16
    conv_all<<<(unsigned)CONV_BLOCKS, 256>>>(x, Wqkv, Wout);

    // 1) QKV projection: M=32768, N=3072, fp16 output
    gemm_mma<0><<<dim3(K3 / 128, MROWS / 128), 128, SMEM_TOTAL>>>(nullptr, nullptr, K3);

    // 2) Patch attention (fp16 in/out, fp32 math)
    attn_kernel<<<dim3(RR, NHEADS, BATCH), 256>>>();

    // 3) Output projection + bias: M=32768, N=1024, fp32 output
    gemm_mma<1><<<dim3(DIMC / 128, MROWS / 128), 128, SMEM_TOTAL>>>(bout, out, DIMC);
}